// round 10
// baseline (speedup 1.0000x reference)
#include <cuda_runtime.h>
#include <cstdint>

#define L_SEQ   1024
#define KNN     48
#define H       128
#define N_EDGES (L_SEQ * KNN)       // 49152
#define TILE_E  64
#define N_TILES (N_EDGES / TILE_E)  // 768
#define GRID_MAIN 296
#define NTHREADS 256

__device__ float d_hv[L_SEQ * H];   // LN+W1 output (512 KB scratch)

// smem layout (bytes), per CTA (65.7 KB -> 2 CTAs/SM)
#define SM_P     0                     // P hi (16K) ; also W2-hi temp at startup
#define P_LO_OFF 16384                 // P lo (16K)
#define SM_W2LO  32768                 // W2 lo (32K, persistent)
#define SM_B2    65536
#define SM_TOTAL (65536 + 512 + 128)   // 66176 B

// ---------------------------------------------------------------------------
__device__ __forceinline__ uint32_t smem_to_u32(const void* p) {
    uint32_t a;
    asm("{ .reg .u64 t; cvta.to.shared.u64 t, %1; cvt.u32.u64 %0, t; }"
        : "=r"(a) : "l"(p));
    return a;
}

// XOR swizzle on 16B chunks within a 256B row (conflict-free ldmatrix/STS)
__device__ __forceinline__ uint32_t swz(uint32_t row, uint32_t chunk) {
    return (chunk & 8u) | ((chunk ^ row) & 7u);
}

// split (a,b) fp32 pair into packed bf16x2 hi + bf16x2 lo (a -> low 16 bits)
__device__ __forceinline__ void split2(float a, float b, uint32_t& hi, uint32_t& lo) {
    uint32_t h;
    asm("cvt.rn.bf16x2.f32 %0, %1, %2;" : "=r"(h) : "f"(b), "f"(a));
    float ha = __uint_as_float(h << 16);
    float hb = __uint_as_float(h & 0xFFFF0000u);
    float la = a - ha;
    float lb = b - hb;
    asm("cvt.rn.bf16x2.f32 %0, %1, %2;" : "=r"(lo) : "f"(lb), "f"(la));
    hi = h;
}

__device__ __forceinline__ void ldsm_x4(uint32_t* r, uint32_t addr) {
    asm volatile("ldmatrix.sync.aligned.m8n8.x4.shared.b16 {%0,%1,%2,%3}, [%4];"
                 : "=r"(r[0]), "=r"(r[1]), "=r"(r[2]), "=r"(r[3]) : "r"(addr));
}

__device__ __forceinline__ void mma_bf16(float* c, const uint32_t* a,
                                         uint32_t b0, uint32_t b1) {
    asm("mma.sync.aligned.m16n8k16.row.col.f32.bf16.bf16.f32 "
        "{%0,%1,%2,%3}, {%4,%5,%6,%7}, {%8,%9}, {%0,%1,%2,%3};"
        : "+f"(c[0]), "+f"(c[1]), "+f"(c[2]), "+f"(c[3])
        : "r"(a[0]), "r"(a[1]), "r"(a[2]), "r"(a[3]), "r"(b0), "r"(b1));
}

// ---------------------------------------------------------------------------
// Kernel 1: LayerNorm + Linear1 -> d_hv.  8 rows/block, 128 threads, 128 blocks.
// ---------------------------------------------------------------------------
__global__ void __launch_bounds__(128) ln_w1_kernel(
    const float* __restrict__ hV, const float* __restrict__ W1,
    const float* __restrict__ b1, const float* __restrict__ ln_scale,
    const float* __restrict__ ln_bias) {
    __shared__ float xs[8][H];
    int t = threadIdx.x, w = t >> 5, lane = t & 31;
    int i0 = blockIdx.x * 8;

    float4 g = reinterpret_cast<const float4*>(ln_scale)[lane];
    float4 c = reinterpret_cast<const float4*>(ln_bias)[lane];

    #pragma unroll
    for (int rr = 0; rr < 2; rr++) {
        int r = w + rr * 4;
        float4 x = reinterpret_cast<const float4*>(hV + (size_t)(i0 + r) * H)[lane];
        float s = x.x + x.y + x.z + x.w;
        #pragma unroll
        for (int off = 16; off; off >>= 1) s += __shfl_xor_sync(~0u, s, off);
        float mu = s * (1.0f / H);
        float4 d = make_float4(x.x - mu, x.y - mu, x.z - mu, x.w - mu);
        float sq = d.x * d.x + d.y * d.y + d.z * d.z + d.w * d.w;
        #pragma unroll
        for (int off = 16; off; off >>= 1) sq += __shfl_xor_sync(~0u, sq, off);
        float rs = rsqrtf(sq * (1.0f / H) + 1e-5f);
        float4 o = make_float4(d.x * rs * g.x + c.x, d.y * rs * g.y + c.y,
                               d.z * rs * g.z + c.z, d.w * rs * g.w + c.w);
        reinterpret_cast<float4*>(xs[r])[lane] = o;
    }
    __syncthreads();

    float acc[8];
    float bt = b1[t];
    #pragma unroll
    for (int r = 0; r < 8; r++) acc[r] = bt;
    const float4* wrow = reinterpret_cast<const float4*>(W1 + (size_t)t * H);
    #pragma unroll 4
    for (int q = 0; q < H / 4; q++) {
        float4 w4 = wrow[q];
        #pragma unroll
        for (int r = 0; r < 8; r++) {
            float4 x4 = reinterpret_cast<const float4*>(xs[r])[q];
            acc[r] += w4.x * x4.x + w4.y * x4.y + w4.z * x4.z + w4.w * x4.w;
        }
    }
    #pragma unroll
    for (int r = 0; r < 8; r++) d_hv[(size_t)(i0 + r) * H + t] = acc[r];
}

// ---------------------------------------------------------------------------
// Kernel 2: C[49152,128] = P @ W2^T, A-stationary (W2-hi in regs), 64-edge
// tiles, 2 CTAs/SM for barrier-decoupled phase overlap.
// 256 thr = 8 warps, warp = m16 outputs x n64 edges, K=128, 3-term bf16.
// ---------------------------------------------------------------------------
__global__ void __launch_bounds__(NTHREADS, 2) outer_w2_mma_kernel(
    const int* __restrict__ Eidx, const float* __restrict__ W2,
    const float* __restrict__ b2, float* __restrict__ out) {
    extern __shared__ char smemc[];
    const uint32_t sb = smem_to_u32(smemc);
    int t = threadIdx.x;
    int warp = t >> 5, lane = t & 31;
    int wm = warp;          // 0..7  m16 output tile

    // ---- stage W2: hi into P area (temp), lo into persistent SM_W2LO; b2 ----
    for (int g = t; g < 2048; g += NTHREADS) {
        int o = g >> 4;                // output feature row
        int ch = g & 15;               // 16B chunk within row
        const float4* w = reinterpret_cast<const float4*>(W2 + (size_t)o * H + ch * 8);
        float4 w0 = w[0], w1 = w[1];
        uint4 hi4, lo4;
        split2(w0.x, w0.y, hi4.x, lo4.x);
        split2(w0.z, w0.w, hi4.y, lo4.y);
        split2(w1.x, w1.y, hi4.z, lo4.z);
        split2(w1.z, w1.w, hi4.w, lo4.w);
        uint32_t off = (uint32_t)o * 256 + swz(o, ch) * 16;
        *reinterpret_cast<uint4*>(smemc + SM_P + off) = hi4;     // temp
        *reinterpret_cast<uint4*>(smemc + SM_W2LO + off) = lo4;  // persistent
    }
    if (t < 128) reinterpret_cast<float*>(smemc + SM_B2)[t] = b2[t];
    __syncthreads();

    // ---- preload A-hi fragments (W2-hi rows wm*16..+15, all K) ----
    const uint32_t m_a   = (uint32_t)(wm * 16 + (lane & 15));
    const uint32_t a_sel = (uint32_t)(lane >> 4);
    uint32_t ah[8][4];
    #pragma unroll
    for (int f = 0; f < 8; f++) {
        uint32_t chunkA = (uint32_t)(2 * f) + a_sel;
        ldsm_x4(ah[f], sb + SM_P + m_a * 256 + swz(m_a, chunkA) * 16);
    }
    const uint32_t alo_row = sb + SM_W2LO + m_a * 256;
    __syncthreads();   // W2-hi temp in P area is dead after this

    // B-side (P) ldmatrix address components
    const uint32_t b_row7   = (uint32_t)(lane & 7);
    const uint32_t b_rowoff = b_row7 * 256;
    const uint32_t b_sel    = (uint32_t)(lane >> 3);

    // epilogue constants
    const int o0 = wm * 16 + (lane >> 2);
    const float b2a = reinterpret_cast<const float*>(smemc + SM_B2)[o0];
    const float b2b = reinterpret_cast<const float*>(smemc + SM_B2)[o0 + 8];

    for (int tile = blockIdx.x; tile < N_TILES; tile += gridDim.x) {
        // ---- build P hi/lo (gather); 4 threads/edge, 64 edges ----
        {
            int m  = t >> 2;             // edge row in tile (0..63)
            int q4 = t & 3;              // h quarter (32 values)
            int e = tile * TILE_E + m;
            int i = (int)((unsigned)e / KNN);
            int j = __ldg(Eidx + e);
            const float4* pi = reinterpret_cast<const float4*>(
                d_hv + (size_t)i * H + q4 * 32);
            const float4* pj = reinterpret_cast<const float4*>(
                d_hv + (size_t)j * H + q4 * 32);
            uint32_t rowbase = (uint32_t)m * 256;
            #pragma unroll
            for (int q = 0; q < 4; q++) {
                float4 x0 = pi[2 * q], x1 = pi[2 * q + 1];
                float4 y0 = pj[2 * q], y1 = pj[2 * q + 1];
                uint4 hi4, lo4;
                split2(x0.x * y0.x, x0.y * y0.y, hi4.x, lo4.x);
                split2(x0.z * y0.z, x0.w * y0.w, hi4.y, lo4.y);
                split2(x1.x * y1.x, x1.y * y1.y, hi4.z, lo4.z);
                split2(x1.z * y1.z, x1.w * y1.w, hi4.w, lo4.w);
                uint32_t off = rowbase + swz((uint32_t)m, (uint32_t)(q4 * 4 + q)) * 16;
                *reinterpret_cast<uint4*>(smemc + SM_P + off) = hi4;
                *reinterpret_cast<uint4*>(smemc + SM_P + P_LO_OFF + off) = lo4;
            }
        }
        __syncthreads();

        // ---- mma: m16 x n64, K=128, 3-term bf16 split ----
        float acc[8][4];
        #pragma unroll
        for (int nt = 0; nt < 8; nt++)
            #pragma unroll
            for (int q = 0; q < 4; q++) acc[nt][q] = 0.0f;

        #pragma unroll
        for (int kp = 0; kp < 4; kp++) {        // k32 steps
            uint32_t al0[4], al1[4];
            ldsm_x4(al0, alo_row + swz(m_a, (uint32_t)(4 * kp) + a_sel) * 16);
            ldsm_x4(al1, alo_row + swz(m_a, (uint32_t)(4 * kp + 2) + a_sel) * 16);

            uint32_t chunkB = (uint32_t)(kp * 4) + b_sel;
            uint32_t bcol = swz(b_row7, chunkB) * 16;
            #pragma unroll
            for (int nt = 0; nt < 8; nt++) {
                uint32_t baddr = sb + SM_P + (uint32_t)nt * 2048 + b_rowoff + bcol;
                uint32_t bh[4], bl[4];
                ldsm_x4(bh, baddr);
                ldsm_x4(bl, baddr + P_LO_OFF);
                mma_bf16(acc[nt], ah[2 * kp],     bh[0], bh[1]);  // hi*hi (k lo)
                mma_bf16(acc[nt], ah[2 * kp],     bl[0], bl[1]);  // hi*lo
                mma_bf16(acc[nt], al0,            bh[0], bh[1]);  // lo*hi
                mma_bf16(acc[nt], ah[2 * kp + 1], bh[2], bh[3]);  // hi*hi (k hi)
                mma_bf16(acc[nt], ah[2 * kp + 1], bl[2], bl[3]);  // hi*lo
                mma_bf16(acc[nt], al1,            bh[2], bh[3]);  // lo*hi
            }
        }

        // ---- epilogue: C[m=o, n=e] -> out[e][o] + b2 ----
        {
            int e_base = tile * TILE_E + (lane & 3) * 2;
            #pragma unroll
            for (int nt = 0; nt < 8; nt++) {
                int e = e_base + nt * 8;
                float* p0 = out + (size_t)e * H;
                p0[o0]         = acc[nt][0] + b2a;
                p0[H + o0]     = acc[nt][1] + b2a;
                p0[o0 + 8]     = acc[nt][2] + b2b;
                p0[H + o0 + 8] = acc[nt][3] + b2b;
            }
        }
        __syncthreads();   // all warps done reading P before next build
    }
}

// ---------------------------------------------------------------------------
extern "C" void kernel_launch(void* const* d_in, const int* in_sizes, int n_in,
                              void* d_out, int out_size) {
    const float* hV       = (const float*)d_in[0];
    const int*   Eidx     = (const int*)d_in[1];
    const float* W1       = (const float*)d_in[2];
    const float* b1       = (const float*)d_in[3];
    const float* W2       = (const float*)d_in[4];
    const float* b2       = (const float*)d_in[5];
    const float* ln_scale = (const float*)d_in[6];
    const float* ln_bias  = (const float*)d_in[7];
    float* out = (float*)d_out;

    cudaFuncSetAttribute(outer_w2_mma_kernel,
                         cudaFuncAttributeMaxDynamicSharedMemorySize, SM_TOTAL);

    ln_w1_kernel<<<L_SEQ / 8, 128>>>(hV, W1, b1, ln_scale, ln_bias);
    outer_w2_mma_kernel<<<GRID_MAIN, NTHREADS, SM_TOTAL>>>(Eidx, W2, b2, out);
}

// round 12
// speedup vs baseline: 1.0500x; 1.0500x over previous
#include <cuda_runtime.h>
#include <cstdint>

#define L_SEQ   1024
#define KNN     48
#define H       128
#define N_EDGES (L_SEQ * KNN)       // 49152
#define N_GRP   (N_EDGES / 8)       // 6144 edge groups of 8
#define GRID_MAIN 444
#define NTHREADS 128

__device__ float d_hv[L_SEQ * H];   // LN+W1 output (512 KB scratch)

// smem (prologue only): W2 hi / lo staged k-permuted + swizzled
#define SM_HI 0
#define SM_LO 32768
#define SM_TOTAL 65536

// ---------------------------------------------------------------------------
__device__ __forceinline__ uint32_t smem_to_u32(const void* p) {
    uint32_t a;
    asm("{ .reg .u64 t; cvta.to.shared.u64 t, %1; cvt.u32.u64 %0, t; }"
        : "=r"(a) : "l"(p));
    return a;
}
__device__ __forceinline__ uint32_t swz(uint32_t row, uint32_t chunk) {
    return (chunk & 8u) | ((chunk ^ row) & 7u);
}
// split (a,b) fp32 pair -> packed bf16x2 hi + lo (a in low 16 bits)
__device__ __forceinline__ void split2(float a, float b, uint32_t& hi, uint32_t& lo) {
    uint32_t h;
    asm("cvt.rn.bf16x2.f32 %0, %1, %2;" : "=r"(h) : "f"(b), "f"(a));
    float ha = __uint_as_float(h << 16);
    float hb = __uint_as_float(h & 0xFFFF0000u);
    asm("cvt.rn.bf16x2.f32 %0, %1, %2;" : "=r"(lo) : "f"(b - hb), "f"(a - ha));
    hi = h;
}
__device__ __forceinline__ void ldsm_x4(uint32_t* r, uint32_t addr) {
    asm volatile("ldmatrix.sync.aligned.m8n8.x4.shared.b16 {%0,%1,%2,%3}, [%4];"
                 : "=r"(r[0]), "=r"(r[1]), "=r"(r[2]), "=r"(r[3]) : "r"(addr));
}
__device__ __forceinline__ void mma_bf16(float* c, const uint32_t* a,
                                         uint32_t b0, uint32_t b1) {
    asm("mma.sync.aligned.m16n8k16.row.col.f32.bf16.bf16.f32 "
        "{%0,%1,%2,%3}, {%4,%5,%6,%7}, {%8,%9}, {%0,%1,%2,%3};"
        : "+f"(c[0]), "+f"(c[1]), "+f"(c[2]), "+f"(c[3])
        : "r"(a[0]), "r"(a[1]), "r"(a[2]), "r"(a[3]), "r"(b0), "r"(b1));
}

// ---------------------------------------------------------------------------
// Kernel 1: LayerNorm + Linear1 -> d_hv.  8 rows/block, 128 threads.
// ---------------------------------------------------------------------------
__global__ void __launch_bounds__(128) ln_w1_kernel(
    const float* __restrict__ hV, const float* __restrict__ W1,
    const float* __restrict__ b1, const float* __restrict__ ln_scale,
    const float* __restrict__ ln_bias) {
    __shared__ float xs[8][H];
    int t = threadIdx.x, w = t >> 5, lane = t & 31;
    int i0 = blockIdx.x * 8;

    float4 g = reinterpret_cast<const float4*>(ln_scale)[lane];
    float4 c = reinterpret_cast<const float4*>(ln_bias)[lane];

    #pragma unroll
    for (int rr = 0; rr < 2; rr++) {
        int r = w + rr * 4;
        float4 x = reinterpret_cast<const float4*>(hV + (size_t)(i0 + r) * H)[lane];
        float s = x.x + x.y + x.z + x.w;
        #pragma unroll
        for (int off = 16; off; off >>= 1) s += __shfl_xor_sync(~0u, s, off);
        float mu = s * (1.0f / H);
        float4 d = make_float4(x.x - mu, x.y - mu, x.z - mu, x.w - mu);
        float sq = d.x * d.x + d.y * d.y + d.z * d.z + d.w * d.w;
        #pragma unroll
        for (int off = 16; off; off >>= 1) sq += __shfl_xor_sync(~0u, sq, off);
        float rs = rsqrtf(sq * (1.0f / H) + 1e-5f);
        float4 o = make_float4(d.x * rs * g.x + c.x, d.y * rs * g.y + c.y,
                               d.z * rs * g.z + c.z, d.w * rs * g.w + c.w);
        reinterpret_cast<float4*>(xs[r])[lane] = o;
    }
    __syncthreads();

    float acc[8];
    float bt = b1[t];
    #pragma unroll
    for (int r = 0; r < 8; r++) acc[r] = bt;
    const float4* wrow = reinterpret_cast<const float4*>(W1 + (size_t)t * H);
    #pragma unroll 4
    for (int q = 0; q < H / 4; q++) {
        float4 w4 = wrow[q];
        #pragma unroll
        for (int r = 0; r < 8; r++) {
            float4 x4 = reinterpret_cast<const float4*>(xs[r])[q];
            acc[r] += w4.x * x4.x + w4.y * x4.y + w4.z * x4.z + w4.w * x4.w;
        }
    }
    #pragma unroll
    for (int r = 0; r < 8; r++) d_hv[(size_t)(i0 + r) * H + t] = acc[r];
}

// ---------------------------------------------------------------------------
// Kernel 2: register-direct-B GEMM.  No smem / barriers in the main loop.
//   K permutation: k = 2*(j&3)+eps + 8s + 16d + 32c  <->  h = 8j + eps+2s+4d,
//   j&3 = lane%4 class, c = j>>2.  Applied to both W2 staging and B build.
// 128 thr = 4 warps, warp = m32 outputs (A = W2 hi/lo in 128 regs),
// loop over n8 edge groups: build B frags from d_hv loads, 48 mma, 8 STG.
// ---------------------------------------------------------------------------
__global__ void __launch_bounds__(NTHREADS, 3) outer_w2_mma_kernel(
    const int* __restrict__ Eidx, const float* __restrict__ W2,
    const float* __restrict__ b2, float* __restrict__ out) {
    extern __shared__ char smemc[];
    const uint32_t sb = smem_to_u32(smemc);
    int t = threadIdx.x;
    int wm = t >> 5, lane = t & 31;

    // ---- prologue: stage W2 hi/lo, k-permuted + swizzled ----
    for (int idx = t; idx < 2048; idx += NTHREADS) {
        int o = idx >> 4;       // output row
        int j = idx & 15;       // h-window of 8
        const float4* w = reinterpret_cast<const float4*>(W2 + (size_t)o * H + j * 8);
        float4 w0 = w[0], w1 = w[1];
        float v[8] = {w0.x, w0.y, w0.z, w0.w, w1.x, w1.y, w1.z, w1.w};
        #pragma unroll
        for (int p = 0; p < 4; p++) {          // p = s + 2d
            uint32_t hi, lo;
            split2(v[2 * p], v[2 * p + 1], hi, lo);
            uint32_t ch = (uint32_t)(p + 4 * (j >> 2));
            uint32_t boff = (uint32_t)o * 256 + swz((uint32_t)o, ch) * 16 + (j & 3) * 4;
            *reinterpret_cast<uint32_t*>(smemc + SM_HI + boff) = hi;
            *reinterpret_cast<uint32_t*>(smemc + SM_LO + boff) = lo;
        }
    }
    __syncthreads();

    // ---- preload A fragments: m32 (2 x m16) x k128 hi+lo ----
    uint32_t ah[2][8][4], al[2][8][4];
    {
        uint32_t a_sel = (uint32_t)(lane >> 4);
        #pragma unroll
        for (int s = 0; s < 2; s++) {
            uint32_t mrow = (uint32_t)(wm * 32 + s * 16 + (lane & 15));
            uint32_t rowoff = mrow * 256;
            #pragma unroll
            for (int f = 0; f < 8; f++) {
                uint32_t coff = swz(mrow, (uint32_t)(2 * f) + a_sel) * 16;
                ldsm_x4(ah[s][f], sb + SM_HI + rowoff + coff);
                ldsm_x4(al[s][f], sb + SM_LO + rowoff + coff);
            }
        }
    }

    // epilogue constants
    const int ob = wm * 32 + (lane >> 2);
    const float b2v[4] = {__ldg(b2 + ob), __ldg(b2 + ob + 8),
                          __ldg(b2 + ob + 16), __ldg(b2 + ob + 24)};
    const int hq = (lane & 3) * 8;          // this lane's h base within a row

    // ---- main loop: no smem, no barriers ----
    for (int g = blockIdx.x; g < N_GRP; g += gridDim.x) {
        int e = g * 8 + (lane >> 2);
        int je = __ldg(Eidx + e);
        int ie = (int)((unsigned)e / KNN);
        const float4* pj = reinterpret_cast<const float4*>(d_hv + (size_t)je * H + hq);
        const float4* pi = reinterpret_cast<const float4*>(d_hv + (size_t)ie * H + hq);

        float acc[2][4];
        #pragma unroll
        for (int s = 0; s < 2; s++)
            #pragma unroll
            for (int q = 0; q < 4; q++) acc[s][q] = 0.0f;

        #pragma unroll
        for (int c = 0; c < 4; c++) {       // k32 blocks
            float4 xj0 = pj[8 * c], xj1 = pj[8 * c + 1];
            float4 xi0 = pi[8 * c], xi1 = pi[8 * c + 1];
            float4 p0 = make_float4(xi0.x * xj0.x, xi0.y * xj0.y,
                                    xi0.z * xj0.z, xi0.w * xj0.w);
            float4 p1 = make_float4(xi1.x * xj1.x, xi1.y * xj1.y,
                                    xi1.z * xj1.z, xi1.w * xj1.w);
            uint32_t b00h, b00l, b01h, b01l, b10h, b10l, b11h, b11l;
            split2(p0.x, p0.y, b00h, b00l);   // d=0, s=0 (k8 low)
            split2(p0.z, p0.w, b01h, b01l);   // d=0, s=1 (k8 high)
            split2(p1.x, p1.y, b10h, b10l);   // d=1, s=0
            split2(p1.z, p1.w, b11h, b11l);   // d=1, s=1
            #pragma unroll
            for (int s = 0; s < 2; s++) {
                mma_bf16(acc[s], ah[s][2 * c],     b00h, b01h);  // hi*hi
                mma_bf16(acc[s], ah[s][2 * c],     b00l, b01l);  // hi*lo
                mma_bf16(acc[s], al[s][2 * c],     b00h, b01h);  // lo*hi
                mma_bf16(acc[s], ah[s][2 * c + 1], b10h, b11h);
                mma_bf16(acc[s], ah[s][2 * c + 1], b10l, b11l);
                mma_bf16(acc[s], al[s][2 * c + 1], b10h, b11h);
            }
        }

        // ---- epilogue: C[m=o, n=e] -> out[e][o] + b2 ----
        int e0 = g * 8 + 2 * (lane & 3);
        float* r0 = out + (size_t)e0 * H;
        float* r1 = r0 + H;
        #pragma unroll
        for (int s = 0; s < 2; s++) {
            int o = ob + 16 * s;
            r0[o]     = acc[s][0] + b2v[2 * s];
            r1[o]     = acc[s][1] + b2v[2 * s];
            r0[o + 8] = acc[s][2] + b2v[2 * s + 1];
            r1[o + 8] = acc[s][3] + b2v[2 * s + 1];
        }
    }
}

// ---------------------------------------------------------------------------
extern "C" void kernel_launch(void* const* d_in, const int* in_sizes, int n_in,
                              void* d_out, int out_size) {
    const float* hV       = (const float*)d_in[0];
    const int*   Eidx     = (const int*)d_in[1];
    const float* W1       = (const float*)d_in[2];
    const float* b1       = (const float*)d_in[3];
    const float* W2       = (const float*)d_in[4];
    const float* b2       = (const float*)d_in[5];
    const float* ln_scale = (const float*)d_in[6];
    const float* ln_bias  = (const float*)d_in[7];
    float* out = (float*)d_out;

    cudaFuncSetAttribute(outer_w2_mma_kernel,
                         cudaFuncAttributeMaxDynamicSharedMemorySize, SM_TOTAL);

    ln_w1_kernel<<<L_SEQ / 8, 128>>>(hV, W1, b1, ln_scale, ln_bias);
    outer_w2_mma_kernel<<<GRID_MAIN, NTHREADS, SM_TOTAL>>>(Eidx, W2, b2, out);
}

// round 14
// speedup vs baseline: 1.3781x; 1.3125x over previous
#include <cuda_runtime.h>
#include <cstdint>

#define L_SEQ   1024
#define KNN     48
#define H       128
#define N_EDGES (L_SEQ * KNN)       // 49152
#define N_GRP   (N_EDGES / 8)       // 6144 edge groups of 8
#define GRID_MAIN 592
#define NTHREADS 128

__device__ float d_hv[L_SEQ * H];   // LN+W1 output (512 KB scratch)

// smem (prologue only): W2 fp16 staged k-permuted + swizzled, 256 B per o-row
#define SM_TOTAL 32768

// ---------------------------------------------------------------------------
__device__ __forceinline__ uint32_t smem_to_u32(const void* p) {
    uint32_t a;
    asm("{ .reg .u64 t; cvta.to.shared.u64 t, %1; cvt.u32.u64 %0, t; }"
        : "=r"(a) : "l"(p));
    return a;
}
__device__ __forceinline__ uint32_t swz(uint32_t row, uint32_t chunk) {
    return (chunk & 8u) | ((chunk ^ row) & 7u);
}
// pack (a,b) fp32 -> fp16x2 with a in low 16 bits
__device__ __forceinline__ uint32_t pack_f16(float a, float b) {
    uint32_t r;
    asm("cvt.rn.f16x2.f32 %0, %1, %2;" : "=r"(r) : "f"(b), "f"(a));
    return r;
}
__device__ __forceinline__ void ldsm_x4(uint32_t* r, uint32_t addr) {
    asm volatile("ldmatrix.sync.aligned.m8n8.x4.shared.b16 {%0,%1,%2,%3}, [%4];"
                 : "=r"(r[0]), "=r"(r[1]), "=r"(r[2]), "=r"(r[3]) : "r"(addr));
}
__device__ __forceinline__ void mma_f16(float* c, const uint32_t* a,
                                        uint32_t b0, uint32_t b1) {
    asm("mma.sync.aligned.m16n8k16.row.col.f32.f16.f16.f32 "
        "{%0,%1,%2,%3}, {%4,%5,%6,%7}, {%8,%9}, {%0,%1,%2,%3};"
        : "+f"(c[0]), "+f"(c[1]), "+f"(c[2]), "+f"(c[3])
        : "r"(a[0]), "r"(a[1]), "r"(a[2]), "r"(a[3]), "r"(b0), "r"(b1));
}

// ---------------------------------------------------------------------------
// Kernel 1: LayerNorm + Linear1 -> d_hv.  8 rows/block, 128 threads.
// ---------------------------------------------------------------------------
__global__ void __launch_bounds__(128) ln_w1_kernel(
    const float* __restrict__ hV, const float* __restrict__ W1,
    const float* __restrict__ b1, const float* __restrict__ ln_scale,
    const float* __restrict__ ln_bias) {
    __shared__ float xs[8][H];
    int t = threadIdx.x, w = t >> 5, lane = t & 31;
    int i0 = blockIdx.x * 8;

    float4 g = reinterpret_cast<const float4*>(ln_scale)[lane];
    float4 c = reinterpret_cast<const float4*>(ln_bias)[lane];

    #pragma unroll
    for (int rr = 0; rr < 2; rr++) {
        int r = w + rr * 4;
        float4 x = reinterpret_cast<const float4*>(hV + (size_t)(i0 + r) * H)[lane];
        float s = x.x + x.y + x.z + x.w;
        #pragma unroll
        for (int off = 16; off; off >>= 1) s += __shfl_xor_sync(~0u, s, off);
        float mu = s * (1.0f / H);
        float4 d = make_float4(x.x - mu, x.y - mu, x.z - mu, x.w - mu);
        float sq = d.x * d.x + d.y * d.y + d.z * d.z + d.w * d.w;
        #pragma unroll
        for (int off = 16; off; off >>= 1) sq += __shfl_xor_sync(~0u, sq, off);
        float rs = rsqrtf(sq * (1.0f / H) + 1e-5f);
        float4 o = make_float4(d.x * rs * g.x + c.x, d.y * rs * g.y + c.y,
                               d.z * rs * g.z + c.z, d.w * rs * g.w + c.w);
        reinterpret_cast<float4*>(xs[r])[lane] = o;
    }
    __syncthreads();

    float acc[8];
    float bt = b1[t];
    #pragma unroll
    for (int r = 0; r < 8; r++) acc[r] = bt;
    const float4* wrow = reinterpret_cast<const float4*>(W1 + (size_t)t * H);
    #pragma unroll 4
    for (int q = 0; q < H / 4; q++) {
        float4 w4 = wrow[q];
        #pragma unroll
        for (int r = 0; r < 8; r++) {
            float4 x4 = reinterpret_cast<const float4*>(xs[r])[q];
            acc[r] += w4.x * x4.x + w4.y * x4.y + w4.z * x4.z + w4.w * x4.w;
        }
    }
    #pragma unroll
    for (int r = 0; r < 8; r++) d_hv[(size_t)(i0 + r) * H + t] = acc[r];
}

// ---------------------------------------------------------------------------
// Kernel 2: single-term fp16 register-direct-B GEMM.  No smem / barriers in
// the main loop.  K permutation (as round 12) applied to W2 staging + B build.
// 128 thr = 4 warps, warp = m32 outputs (A = W2 fp16 in 64 regs),
// loop over n8 edge groups: 16 LDG.128, 4 packs, 16 mma, 8 STG per warp.
// ---------------------------------------------------------------------------
__global__ void __launch_bounds__(NTHREADS, 4) outer_w2_mma_kernel(
    const int* __restrict__ Eidx, const float* __restrict__ W2,
    const float* __restrict__ b2, float* __restrict__ out) {
    extern __shared__ char smemc[];
    const uint32_t sb = smem_to_u32(smemc);
    int t = threadIdx.x;
    int wm = t >> 5, lane = t & 31;

    // ---- prologue: stage W2 fp16, k-permuted + swizzled ----
    for (int idx = t; idx < 2048; idx += NTHREADS) {
        int o = idx >> 4;       // output row
        int j = idx & 15;       // h-window of 8
        const float4* w = reinterpret_cast<const float4*>(W2 + (size_t)o * H + j * 8);
        float4 w0 = w[0], w1 = w[1];
        float v[8] = {w0.x, w0.y, w0.z, w0.w, w1.x, w1.y, w1.z, w1.w};
        #pragma unroll
        for (int p = 0; p < 4; p++) {          // p = s + 2d
            uint32_t hv16 = pack_f16(v[2 * p], v[2 * p + 1]);
            uint32_t ch = (uint32_t)(p + 4 * (j >> 2));
            uint32_t boff = (uint32_t)o * 256 + swz((uint32_t)o, ch) * 16 + (j & 3) * 4;
            *reinterpret_cast<uint32_t*>(smemc + boff) = hv16;
        }
    }
    __syncthreads();

    // ---- preload A fragments: m32 (2 x m16) x k128 ----
    uint32_t ah[2][8][4];
    {
        uint32_t a_sel = (uint32_t)(lane >> 4);
        #pragma unroll
        for (int s = 0; s < 2; s++) {
            uint32_t mrow = (uint32_t)(wm * 32 + s * 16 + (lane & 15));
            uint32_t rowoff = mrow * 256;
            #pragma unroll
            for (int f = 0; f < 8; f++) {
                uint32_t coff = swz(mrow, (uint32_t)(2 * f) + a_sel) * 16;
                ldsm_x4(ah[s][f], sb + rowoff + coff);
            }
        }
    }

    // epilogue constants
    const int ob = wm * 32 + (lane >> 2);
    const float b2v[4] = {__ldg(b2 + ob), __ldg(b2 + ob + 8),
                          __ldg(b2 + ob + 16), __ldg(b2 + ob + 24)};
    const int hq = (lane & 3) * 8;          // this lane's h base within a row

    // ---- main loop: no smem, no barriers ----
    for (int g = blockIdx.x; g < N_GRP; g += gridDim.x) {
        int e = g * 8 + (lane >> 2);
        int je = __ldg(Eidx + e);
        int ie = (int)((unsigned)e / KNN);
        const float4* pj = reinterpret_cast<const float4*>(d_hv + (size_t)je * H + hq);
        const float4* pi = reinterpret_cast<const float4*>(d_hv + (size_t)ie * H + hq);

        float acc[2][4];
        #pragma unroll
        for (int s = 0; s < 2; s++)
            #pragma unroll
            for (int q = 0; q < 4; q++) acc[s][q] = 0.0f;

        #pragma unroll
        for (int c = 0; c < 4; c++) {       // k32 blocks
            float4 xj0 = pj[8 * c], xj1 = pj[8 * c + 1];
            float4 xi0 = pi[8 * c], xi1 = pi[8 * c + 1];
            uint32_t b00 = pack_f16(xi0.x * xj0.x, xi0.y * xj0.y);  // d=0, k8 low
            uint32_t b01 = pack_f16(xi0.z * xj0.z, xi0.w * xj0.w);  // d=0, k8 high
            uint32_t b10 = pack_f16(xi1.x * xj1.x, xi1.y * xj1.y);  // d=1, k8 low
            uint32_t b11 = pack_f16(xi1.z * xj1.z, xi1.w * xj1.w);  // d=1, k8 high
            #pragma unroll
            for (int s = 0; s < 2; s++) {
                mma_f16(acc[s], ah[s][2 * c],     b00, b01);
                mma_f16(acc[s], ah[s][2 * c + 1], b10, b11);
            }
        }

        // ---- epilogue: C[m=o, n=e] -> out[e][o] + b2 ----
        int e0 = g * 8 + 2 * (lane & 3);
        float* r0 = out + (size_t)e0 * H;
        float* r1 = r0 + H;
        #pragma unroll
        for (int s = 0; s < 2; s++) {
            int o = ob + 16 * s;
            r0[o]     = acc[s][0] + b2v[2 * s];
            r1[o]     = acc[s][1] + b2v[2 * s];
            r0[o + 8] = acc[s][2] + b2v[2 * s + 1];
            r1[o + 8] = acc[s][3] + b2v[2 * s + 1];
        }
    }
}

// ---------------------------------------------------------------------------
extern "C" void kernel_launch(void* const* d_in, const int* in_sizes, int n_in,
                              void* d_out, int out_size) {
    const float* hV       = (const float*)d_in[0];
    const int*   Eidx     = (const int*)d_in[1];
    const float* W1       = (const float*)d_in[2];
    const float* b1       = (const float*)d_in[3];
    const float* W2       = (const float*)d_in[4];
    const float* b2       = (const float*)d_in[5];
    const float* ln_scale = (const float*)d_in[6];
    const float* ln_bias  = (const float*)d_in[7];
    float* out = (float*)d_out;

    cudaFuncSetAttribute(outer_w2_mma_kernel,
                         cudaFuncAttributeMaxDynamicSharedMemorySize, SM_TOTAL);

    ln_w1_kernel<<<L_SEQ / 8, 128>>>(hV, W1, b1, ln_scale, ln_bias);
    outer_w2_mma_kernel<<<GRID_MAIN, NTHREADS, SM_TOTAL>>>(Eidx, W2, b2, out);
}

// round 17
// speedup vs baseline: 1.5936x; 1.1564x over previous
#include <cuda_runtime.h>
#include <cuda_fp16.h>
#include <cstdint>

#define L_SEQ   1024
#define KNN     48
#define H       128
#define N_EDGES (L_SEQ * KNN)       // 49152
#define N_GRP   (N_EDGES / 8)       // 6144 edge groups of 8
#define GRID_MAIN 444
#define NTHREADS 128

__device__ __half d_hvh[L_SEQ * H];   // LN+W1 output, fp16 (256 KB scratch)

// smem (prologue only): W2 fp16 staged k-permuted + swizzled, 256 B per o-row
#define SM_TOTAL 32768

// ---------------------------------------------------------------------------
__device__ __forceinline__ uint32_t smem_to_u32(const void* p) {
    uint32_t a;
    asm("{ .reg .u64 t; cvta.to.shared.u64 t, %1; cvt.u32.u64 %0, t; }"
        : "=r"(a) : "l"(p));
    return a;
}
__device__ __forceinline__ uint32_t swz(uint32_t row, uint32_t chunk) {
    return (chunk & 8u) | ((chunk ^ row) & 7u);
}
// pack (a,b) fp32 -> fp16x2 with a in low 16 bits
__device__ __forceinline__ uint32_t pack_f16(float a, float b) {
    uint32_t r;
    asm("cvt.rn.f16x2.f32 %0, %1, %2;" : "=r"(r) : "f"(b), "f"(a));
    return r;
}
__device__ __forceinline__ uint32_t mul2(uint32_t a, uint32_t b) {
    uint32_t r;
    asm("mul.rn.f16x2 %0, %1, %2;" : "=r"(r) : "r"(a), "r"(b));
    return r;
}
__device__ __forceinline__ void ldsm_x4(uint32_t* r, uint32_t addr) {
    asm volatile("ldmatrix.sync.aligned.m8n8.x4.shared.b16 {%0,%1,%2,%3}, [%4];"
                 : "=r"(r[0]), "=r"(r[1]), "=r"(r[2]), "=r"(r[3]) : "r"(addr));
}
__device__ __forceinline__ void mma_f16(float* c, const uint32_t* a,
                                        uint32_t b0, uint32_t b1) {
    asm("mma.sync.aligned.m16n8k16.row.col.f32.f16.f16.f32 "
        "{%0,%1,%2,%3}, {%4,%5,%6,%7}, {%8,%9}, {%0,%1,%2,%3};"
        : "+f"(c[0]), "+f"(c[1]), "+f"(c[2]), "+f"(c[3])
        : "r"(a[0]), "r"(a[1]), "r"(a[2]), "r"(a[3]), "r"(b0), "r"(b1));
}

// ---------------------------------------------------------------------------
// Kernel 1: LayerNorm + Linear1 -> d_hvh (fp16).  8 rows/block, 128 threads.
// ---------------------------------------------------------------------------
__global__ void __launch_bounds__(128) ln_w1_kernel(
    const float* __restrict__ hV, const float* __restrict__ W1,
    const float* __restrict__ b1, const float* __restrict__ ln_scale,
    const float* __restrict__ ln_bias) {
    __shared__ float xs[8][H];
    int t = threadIdx.x, w = t >> 5, lane = t & 31;
    int i0 = blockIdx.x * 8;

    float4 g = reinterpret_cast<const float4*>(ln_scale)[lane];
    float4 c = reinterpret_cast<const float4*>(ln_bias)[lane];

    #pragma unroll
    for (int rr = 0; rr < 2; rr++) {
        int r = w + rr * 4;
        float4 x = reinterpret_cast<const float4*>(hV + (size_t)(i0 + r) * H)[lane];
        float s = x.x + x.y + x.z + x.w;
        #pragma unroll
        for (int off = 16; off; off >>= 1) s += __shfl_xor_sync(~0u, s, off);
        float mu = s * (1.0f / H);
        float4 d = make_float4(x.x - mu, x.y - mu, x.z - mu, x.w - mu);
        float sq = d.x * d.x + d.y * d.y + d.z * d.z + d.w * d.w;
        #pragma unroll
        for (int off = 16; off; off >>= 1) sq += __shfl_xor_sync(~0u, sq, off);
        float rs = rsqrtf(sq * (1.0f / H) + 1e-5f);
        float4 o = make_float4(d.x * rs * g.x + c.x, d.y * rs * g.y + c.y,
                               d.z * rs * g.z + c.z, d.w * rs * g.w + c.w);
        reinterpret_cast<float4*>(xs[r])[lane] = o;
    }
    __syncthreads();

    float acc[8];
    float bt = b1[t];
    #pragma unroll
    for (int r = 0; r < 8; r++) acc[r] = bt;
    const float4* wrow = reinterpret_cast<const float4*>(W1 + (size_t)t * H);
    #pragma unroll 4
    for (int q = 0; q < H / 4; q++) {
        float4 w4 = wrow[q];
        #pragma unroll
        for (int r = 0; r < 8; r++) {
            float4 x4 = reinterpret_cast<const float4*>(xs[r])[q];
            acc[r] += w4.x * x4.x + w4.y * x4.y + w4.z * x4.z + w4.w * x4.w;
        }
    }
    #pragma unroll
    for (int r = 0; r < 8; r++)
        d_hvh[(size_t)(i0 + r) * H + t] = __float2half_rn(acc[r]);
}

// ---------------------------------------------------------------------------
// Kernel 2: single-term fp16 register-direct-B GEMM with fp16 hv table and
// cross-iteration j-prefetch.  No smem / barriers in the main loop.
// 128 thr = 4 warps, warp = m32 outputs (A = W2 fp16 in 64 regs).
// Per 8-edge group/warp: 4 j-LDG.128 (prefetched), 4 i-LDG.128 (broadcast),
// 16 HMUL2, 16 mma, 8 STG.
// ---------------------------------------------------------------------------
__global__ void __launch_bounds__(NTHREADS, 3) outer_w2_mma_kernel(
    const int* __restrict__ Eidx, const float* __restrict__ W2,
    const float* __restrict__ b2, float* __restrict__ out) {
    extern __shared__ char smemc[];
    const uint32_t sb = smem_to_u32(smemc);
    int t = threadIdx.x;
    int wm = t >> 5, lane = t & 31;

    // ---- prologue: stage W2 fp16, k-permuted + swizzled (as round 14) ----
    for (int idx = t; idx < 2048; idx += NTHREADS) {
        int o = idx >> 4;       // output row
        int j = idx & 15;       // h-window of 8
        const float4* w = reinterpret_cast<const float4*>(W2 + (size_t)o * H + j * 8);
        float4 w0 = w[0], w1 = w[1];
        float v[8] = {w0.x, w0.y, w0.z, w0.w, w1.x, w1.y, w1.z, w1.w};
        #pragma unroll
        for (int p = 0; p < 4; p++) {          // p = s + 2d
            uint32_t hv16 = pack_f16(v[2 * p], v[2 * p + 1]);
            uint32_t ch = (uint32_t)(p + 4 * (j >> 2));
            uint32_t boff = (uint32_t)o * 256 + swz((uint32_t)o, ch) * 16 + (j & 3) * 4;
            *reinterpret_cast<uint32_t*>(smemc + boff) = hv16;
        }
    }
    __syncthreads();

    // ---- preload A fragments: m32 (2 x m16) x k128 ----
    uint32_t ah[2][8][4];
    {
        uint32_t a_sel = (uint32_t)(lane >> 4);
        #pragma unroll
        for (int s = 0; s < 2; s++) {
            uint32_t mrow = (uint32_t)(wm * 32 + s * 16 + (lane & 15));
            uint32_t rowoff = mrow * 256;
            #pragma unroll
            for (int f = 0; f < 8; f++) {
                uint32_t coff = swz(mrow, (uint32_t)(2 * f) + a_sel) * 16;
                ldsm_x4(ah[s][f], sb + rowoff + coff);
            }
        }
    }

    // epilogue constants
    const int ob = wm * 32 + (lane >> 2);
    const float b2v[4] = {__ldg(b2 + ob), __ldg(b2 + ob + 8),
                          __ldg(b2 + ob + 16), __ldg(b2 + ob + 24)};
    const int hqh = (lane & 3) * 8;         // this lane's h base (halves)
    const int eoff = lane >> 2;             // edge within group

    // ---- pipelined main loop: no smem, no barriers ----
    int g = blockIdx.x;
    uint4 jv0, jv1, jv2, jv3;
    {
        int je = __ldg(Eidx + g * 8 + eoff);
        const uint4* pj = reinterpret_cast<const uint4*>(
            d_hvh + (size_t)je * H + hqh);
        jv0 = pj[0]; jv1 = pj[4]; jv2 = pj[8]; jv3 = pj[12];
    }

    while (g < N_GRP) {
        int gn = g + (int)gridDim.x;
        uint4 nj0, nj1, nj2, nj3;
        if (gn < N_GRP) {                    // prefetch next group's j rows
            int jen = __ldg(Eidx + gn * 8 + eoff);
            const uint4* pjn = reinterpret_cast<const uint4*>(
                d_hvh + (size_t)jen * H + hqh);
            nj0 = pjn[0]; nj1 = pjn[4]; nj2 = pjn[8]; nj3 = pjn[12];
        }

        int ie = g / 6;                      // 6 groups per node (48/8)
        const uint4* pi = reinterpret_cast<const uint4*>(
            d_hvh + (size_t)ie * H + hqh);   // warp-uniform rows (broadcast)

        float acc[2][4];
        #pragma unroll
        for (int s = 0; s < 2; s++)
            #pragma unroll
            for (int q = 0; q < 4; q++) acc[s][q] = 0.0f;

        #pragma unroll
        for (int c = 0; c < 4; c++) {        // k32 blocks
            uint4 iv = pi[4 * c];
            uint4 jc = (c == 0) ? jv0 : (c == 1) ? jv1 : (c == 2) ? jv2 : jv3;
            uint32_t b0 = mul2(iv.x, jc.x);  // k8 low,  d=0
            uint32_t b1 = mul2(iv.y, jc.y);  // k8 high, d=0
            uint32_t b2_ = mul2(iv.z, jc.z); // k8 low,  d=1
            uint32_t b3 = mul2(iv.w, jc.w);  // k8 high, d=1
            #pragma unroll
            for (int s = 0; s < 2; s++) {
                mma_f16(acc[s], ah[s][2 * c],     b0,  b1);
                mma_f16(acc[s], ah[s][2 * c + 1], b2_, b3);
            }
        }

        // ---- epilogue: C[m=o, n=e] -> out[e][o] + b2 ----
        int e0 = g * 8 + 2 * (lane & 3);
        float* r0 = out + (size_t)e0 * H;
        float* r1 = r0 + H;
        #pragma unroll
        for (int s = 0; s < 2; s++) {
            int o = ob + 16 * s;
            r0[o]     = acc[s][0] + b2v[2 * s];
            r1[o]     = acc[s][1] + b2v[2 * s];
            r0[o + 8] = acc[s][2] + b2v[2 * s + 1];
            r1[o + 8] = acc[s][3] + b2v[2 * s + 1];
        }

        jv0 = nj0; jv1 = nj1; jv2 = nj2; jv3 = nj3;
        g = gn;
    }
}

// ---------------------------------------------------------------------------
extern "C" void kernel_launch(void* const* d_in, const int* in_sizes, int n_in,
                              void* d_out, int out_size) {
    const float* hV       = (const float*)d_in[0];
    const int*   Eidx     = (const int*)d_in[1];
    const float* W1       = (const float*)d_in[2];
    const float* b1       = (const float*)d_in[3];
    const float* W2       = (const float*)d_in[4];
    const float* b2       = (const float*)d_in[5];
    const float* ln_scale = (const float*)d_in[6];
    const float* ln_bias  = (const float*)d_in[7];
    float* out = (float*)d_out;

    cudaFuncSetAttribute(outer_w2_mma_kernel,
                         cudaFuncAttributeMaxDynamicSharedMemorySize, SM_TOTAL);

    ln_w1_kernel<<<L_SEQ / 8, 128>>>(hV, W1, b1, ln_scale, ln_bias);
    outer_w2_mma_kernel<<<GRID_MAIN, NTHREADS, SM_TOTAL>>>(Eidx, W2, b2, out);
}